// round 4
// baseline (speedup 1.0000x reference)
#include <cuda_runtime.h>
#include <cstdint>
#include <cstddef>

// Problem dims
#define B_  512
#define S_  1024
#define I_  64
#define H_  128
#define G_  384   // 3*H
#define C_  10

// Scratch (device globals: allocation APIs are forbidden)
__device__ float g_xg[(size_t)B_ * S_ * G_];    // input-gate preactivations (reused by both layers)
__device__ float g_h1[(size_t)B_ * S_ * H_];    // layer0 hidden outputs
__device__ float g_h2last[B_ * H_];             // last hidden of layer1

typedef unsigned long long u64;

__device__ __forceinline__ u64 pk2(float lo, float hi) {
    u64 r; asm("mov.b64 %0, {%1, %2};" : "=l"(r) : "f"(lo), "f"(hi)); return r;
}
__device__ __forceinline__ void upk2(u64 v, float& lo, float& hi) {
    asm("mov.b64 {%0, %1}, %2;" : "=f"(lo), "=f"(hi) : "l"(v));
}
__device__ __forceinline__ void fma2(u64& d, u64 a, u64 b) {
    asm("fma.rn.f32x2 %0, %1, %2, %0;" : "+l"(d) : "l"(a), "l"(b));
}

// MUFU.TANH — single-op tanh (sm_75+), ~2^-11 rel err
__device__ __forceinline__ float tanh_ap(float x) {
    float y; asm("tanh.approx.f32 %0, %1;" : "=f"(y) : "f"(x)); return y;
}
__device__ __forceinline__ float sig_ap(float x) {
    return fmaf(tanh_ap(0.5f * x), 0.5f, 0.5f);
}

// ============================================================================
// Phase 1/3: xg[m][g] = sum_k A[m][k] * W[g][k] + bias[g]
// Persistent CTAs; W held k-major in smem; 64-row M tiles; fp32x2 FMA.
// Next A tile prefetched into registers while computing the current one.
// ============================================================================
template<int K, bool A_IS_H1>
__global__ __launch_bounds__(256) void gemm_xg_kernel(
    const float* __restrict__ Ain, const float* __restrict__ W,
    const float* __restrict__ bias, int ntiles)
{
    extern __shared__ float smem[];
    float* Ws = smem;              // [K][384], k-major
    float* As = smem + K * G_;     // [64][K]
    const float* A = A_IS_H1 ? g_h1 : Ain;

    const int tid = threadIdx.x;
    constexpr int PF = (64 * K / 4) / 256;   // float4 per thread per tile (4 or 8)

    for (int idx = tid; idx < G_ * (K / 4); idx += 256) {
        int kq = idx / G_;
        int g  = idx - kq * G_;
        float4 w4 = *reinterpret_cast<const float4*>(W + (size_t)g * K + 4 * kq);
        Ws[(4 * kq + 0) * G_ + g] = w4.x;
        Ws[(4 * kq + 1) * G_ + g] = w4.y;
        Ws[(4 * kq + 2) * G_ + g] = w4.z;
        Ws[(4 * kq + 3) * G_ + g] = w4.w;
    }

    const int cg = tid & 31;
    const int rg = tid >> 5;

    float4 bv[3];
#pragma unroll
    for (int gg = 0; gg < 3; ++gg)
        bv[gg] = *reinterpret_cast<const float4*>(bias + gg * H_ + 4 * cg);

    // Prefetch this CTA's first tile into registers
    int tile = blockIdx.x;
    float4 pf[PF];
    if (tile < ntiles) {
        const float4* Ab = reinterpret_cast<const float4*>(A + (size_t)tile * 64 * K);
#pragma unroll
        for (int i = 0; i < PF; ++i) pf[i] = Ab[tid + 256 * i];
    }
    __syncthreads();

    for (; tile < ntiles; tile += gridDim.x) {
        // Deposit prefetched tile
#pragma unroll
        for (int i = 0; i < PF; ++i)
            reinterpret_cast<float4*>(As)[tid + 256 * i] = pf[i];
        __syncthreads();

        // Kick off next tile's loads (latency hidden behind compute)
        int ntile = tile + gridDim.x;
        if (ntile < ntiles) {
            const float4* Ab = reinterpret_cast<const float4*>(A + (size_t)ntile * 64 * K);
#pragma unroll
            for (int i = 0; i < PF; ++i) pf[i] = Ab[tid + 256 * i];
        }

        u64 acc[8][3][2];
#pragma unroll
        for (int r = 0; r < 8; ++r)
#pragma unroll
            for (int gg = 0; gg < 3; ++gg) {
                acc[r][gg][0] = 0ull;
                acc[r][gg][1] = 0ull;
            }

#pragma unroll 2
        for (int k4 = 0; k4 < K; k4 += 4) {
            float4 af[8];
#pragma unroll
            for (int r = 0; r < 8; ++r)
                af[r] = *reinterpret_cast<const float4*>(&As[(rg * 8 + r) * K + k4]);
#pragma unroll
            for (int kk = 0; kk < 4; ++kk) {
                ulonglong2 wp[3];
#pragma unroll
                for (int gg = 0; gg < 3; ++gg)
                    wp[gg] = *reinterpret_cast<const ulonglong2*>(
                        &Ws[(size_t)(k4 + kk) * G_ + gg * H_ + 4 * cg]);
#pragma unroll
                for (int r = 0; r < 8; ++r) {
                    float a = (kk == 0) ? af[r].x : (kk == 1) ? af[r].y
                            : (kk == 2) ? af[r].z : af[r].w;
                    u64 ad = pk2(a, a);
#pragma unroll
                    for (int gg = 0; gg < 3; ++gg) {
                        fma2(acc[r][gg][0], ad, wp[gg].x);
                        fma2(acc[r][gg][1], ad, wp[gg].y);
                    }
                }
            }
        }

        float* Cb = g_xg + (size_t)tile * 64 * G_;
#pragma unroll
        for (int r = 0; r < 8; ++r) {
#pragma unroll
            for (int gg = 0; gg < 3; ++gg) {
                float x0, x1, x2, x3;
                upk2(acc[r][gg][0], x0, x1);
                upk2(acc[r][gg][1], x2, x3);
                float4 o = make_float4(x0 + bv[gg].x, x1 + bv[gg].y,
                                       x2 + bv[gg].z, x3 + bv[gg].w);
                *reinterpret_cast<float4*>(&Cb[(size_t)(rg * 8 + r) * G_ + gg * H_ + 4 * cg]) = o;
            }
        }
        __syncthreads();
    }
}

// ============================================================================
// Phase 2/4: recurrent scan. 128 CTAs x 4 batch rows, 384 threads.
// Thread g owns gate column g; W_hh column as 64 packed u64 k-pairs in regs.
// Dot: software-pipelined (load iter kk+1 while fma'ing iter kk), 4 indep accs.
// Epilogue: sec0/1 publish sigma(r),sigma(z); sec2 publishes raw n-preact+xn;
// then ALL 384 threads share the 512 tanh+blend elements. MUFU.TANH everywhere.
// ============================================================================
template<bool WRITE_ALL>
__global__ __launch_bounds__(384, 1) void gru_rec_kernel(
    const float* __restrict__ Whh, const float* __restrict__ bhh)
{
    __shared__ float  h_s[4][H_];      // row-planar h state
    __shared__ float2 rz[4][H_];       // .x = sigma(r), .y = sigma(z)
    __shared__ float2 gx[4][H_];       // .x = raw n-preact (dot+bh), .y = xn

    const int g  = threadIdx.x;
    const int rb = blockIdx.x * 4;

    // W_hh row as 64 packed (w[2k], w[2k+1]) u64s — loop-invariant, registers
    u64 wp[64];
    const u64* wrow = reinterpret_cast<const u64*>(Whh + (size_t)g * H_);
#pragma unroll
    for (int kk = 0; kk < 64; ++kk) wp[kk] = wrow[kk];
    const float bh = bhh[g];

    for (int idx = g; idx < 4 * H_; idx += 384)
        (&h_s[0][0])[idx] = 0.f;
    __syncthreads();

    const int sec = g >> 7;
    const int j   = g & 127;

    const size_t rstride = (size_t)S_ * G_;
    const float* xp = g_xg + (size_t)rb * rstride + g;

    // Phase-B element assignment: everyone gets e1; sec2 threads get e2 too.
    const int e1   = g;               // 0..383
    const int e2   = g + 128;         // valid only for sec==2 -> 384..511
    const int r1   = e1 >> 7, c1 = e1 & 127;
    const int r2   = e2 >> 7, c2 = e2 & 127;
    float* hout1 = g_h1 + ((size_t)(rb + r1) * S_) * H_ + c1;
    float* hout2 = g_h1 + ((size_t)(rb + r2) * S_) * H_ + c2;

    const ulonglong2* hr0 = reinterpret_cast<const ulonglong2*>(h_s[0]);
    const ulonglong2* hr1 = reinterpret_cast<const ulonglong2*>(h_s[1]);
    const ulonglong2* hr2 = reinterpret_cast<const ulonglong2*>(h_s[2]);
    const ulonglong2* hr3 = reinterpret_cast<const ulonglong2*>(h_s[3]);

    for (int t = 0; t < S_; ++t) {
        // xg loads for the 4 rows: issued now, consumed after the dot
        float xv0 = __ldg(xp);
        float xv1 = __ldg(xp + rstride);
        float xv2 = __ldg(xp + 2 * rstride);
        float xv3 = __ldg(xp + 3 * rstride);
        xp += G_;

        // -------- pipelined dot: h(t-1) . w  for 4 rows --------
        u64 a0 = 0ull, a1 = 0ull, a2 = 0ull, a3 = 0ull;
        ulonglong2 c0 = hr0[0], c1v = hr1[0], c2v = hr2[0], c3v = hr3[0];
#pragma unroll
        for (int kk = 0; kk < 32; ++kk) {
            ulonglong2 n0, n1, n2, n3;
            if (kk < 31) {
                n0 = hr0[kk + 1]; n1 = hr1[kk + 1];
                n2 = hr2[kk + 1]; n3 = hr3[kk + 1];
            }
            u64 w0 = wp[2 * kk];
            u64 w1 = wp[2 * kk + 1];
            fma2(a0, c0.x,  w0);
            fma2(a1, c1v.x, w0);
            fma2(a2, c2v.x, w0);
            fma2(a3, c3v.x, w0);
            fma2(a0, c0.y,  w1);
            fma2(a1, c1v.y, w1);
            fma2(a2, c2v.y, w1);
            fma2(a3, c3v.y, w1);
            if (kk < 31) { c0 = n0; c1v = n1; c2v = n2; c3v = n3; }
        }
        float g0, g1, g2, g3, tlo, thi;
        upk2(a0, tlo, thi); g0 = tlo + thi + bh;
        upk2(a1, tlo, thi); g1 = tlo + thi + bh;
        upk2(a2, tlo, thi); g2 = tlo + thi + bh;
        upk2(a3, tlo, thi); g3 = tlo + thi + bh;

        // -------- phase A: publish gate values --------
        if (sec == 0) {
            rz[0][j].x = sig_ap(xv0 + g0);
            rz[1][j].x = sig_ap(xv1 + g1);
            rz[2][j].x = sig_ap(xv2 + g2);
            rz[3][j].x = sig_ap(xv3 + g3);
        } else if (sec == 1) {
            rz[0][j].y = sig_ap(xv0 + g0);
            rz[1][j].y = sig_ap(xv1 + g1);
            rz[2][j].y = sig_ap(xv2 + g2);
            rz[3][j].y = sig_ap(xv3 + g3);
        } else {
            gx[0][j] = make_float2(g0, xv0);
            gx[1][j] = make_float2(g1, xv1);
            gx[2][j] = make_float2(g2, xv2);
            gx[3][j] = make_float2(g3, xv3);
        }
        __syncthreads();

        // -------- phase B: tanh + blend, spread over all 384 threads --------
        {
            float2 rzv = rz[r1][c1];
            float2 gxv = gx[r1][c1];
            float  ho  = h_s[r1][c1];
            float  n   = tanh_ap(fmaf(rzv.x, gxv.x, gxv.y));
            float  h   = fmaf(rzv.y, ho - n, n);
            h_s[r1][c1] = h;
            if (WRITE_ALL) hout1[0] = h;
            else if (t == S_ - 1) g_h2last[(rb + r1) * H_ + c1] = h;
        }
        if (sec == 2) {
            float2 rzv = rz[r2][c2];
            float2 gxv = gx[r2][c2];
            float  ho  = h_s[r2][c2];
            float  n   = tanh_ap(fmaf(rzv.x, gxv.x, gxv.y));
            float  h   = fmaf(rzv.y, ho - n, n);
            h_s[r2][c2] = h;
            if (WRITE_ALL) hout2[0] = h;
            else if (t == S_ - 1) g_h2last[(rb + r2) * H_ + c2] = h;
        }
        __syncthreads();
        if (WRITE_ALL) { hout1 += H_; hout2 += H_; }
    }
}

// ============================================================================
// Phase 5: out[b][c] = h2last[b] . fc_w[c] + fc_b[c]
// ============================================================================
__global__ __launch_bounds__(128) void fc_kernel(
    const float* __restrict__ fw, const float* __restrict__ fb,
    float* __restrict__ out)
{
    __shared__ float sh[H_];
    const int b = blockIdx.x;
    sh[threadIdx.x] = g_h2last[b * H_ + threadIdx.x];
    __syncthreads();
    if (threadIdx.x < C_) {
        const int c = threadIdx.x;
        float acc = fb[c];
#pragma unroll
        for (int jj = 0; jj < H_; ++jj)
            acc += sh[jj] * fw[c * H_ + jj];
        out[b * C_ + c] = acc;
    }
}

extern "C" void kernel_launch(void* const* d_in, const int* in_sizes, int n_in,
                              void* d_out, int out_size)
{
    (void)in_sizes; (void)n_in; (void)out_size;
    const float* x      = (const float*)d_in[0];
    const float* W_ih0  = (const float*)d_in[1];
    const float* W_hh0  = (const float*)d_in[2];
    const float* b_ih0  = (const float*)d_in[3];
    const float* b_hh0  = (const float*)d_in[4];
    const float* W_ih1  = (const float*)d_in[5];
    const float* W_hh1  = (const float*)d_in[6];
    const float* b_ih1  = (const float*)d_in[7];
    const float* b_hh1  = (const float*)d_in[8];
    const float* fc_w   = (const float*)d_in[9];
    const float* fc_b   = (const float*)d_in[10];
    float* out = (float*)d_out;

    const int ntiles = (B_ * S_) / 64;   // 8192
    const int smem64  = 64  * 4 * (G_ + 64);   // 114688 B
    const int smem128 = 128 * 4 * (G_ + 64);   // 229376 B

    cudaFuncSetAttribute(gemm_xg_kernel<64, false>,
                         cudaFuncAttributeMaxDynamicSharedMemorySize, smem64);
    cudaFuncSetAttribute(gemm_xg_kernel<128, true>,
                         cudaFuncAttributeMaxDynamicSharedMemorySize, smem128);

    // Layer 0
    gemm_xg_kernel<64, false><<<148, 256, smem64>>>(x, W_ih0, b_ih0, ntiles);
    gru_rec_kernel<true><<<128, 384>>>(W_hh0, b_hh0);
    // Layer 1
    gemm_xg_kernel<128, true><<<148, 256, smem128>>>(nullptr, W_ih1, b_ih1, ntiles);
    gru_rec_kernel<false><<<128, 384>>>(W_hh1, b_hh1);
    // Head
    fc_kernel<<<B_, 128>>>(fc_w, fc_b, out);
}